// round 4
// baseline (speedup 1.0000x reference)
#include <cuda_runtime.h>
#include <cstdint>

// Rotation42d: per-sample rotation of (256, 3, 224, 224) fp32 by label in {0,1,2,3}.
//   r0  : out[h][w] = in[h][w]
//   r90 : out[h][w] = in[w][h]
//   r180: out[h][w] = in[H-1-h][w]
//   r270: out[h][w] = in[W-1-w][h]
// 224 = 7*32 -> full 32x32 tiles, no bounds checks.
// All global traffic is 128-bit (float4). Transpose goes through a padded
// shared tile. Label tail (2nd tuple element) fused into the same kernel.

#define HW 224
#define TILES 7  // 224/32

__global__ __launch_bounds__(256) void rot_kernel(
    const float4* __restrict__ x4,
    const int*    __restrict__ label,
    float4*       __restrict__ out4,
    float*        __restrict__ out_tail,   // may be null
    int                         n_tail)
{
    const int img = blockIdx.z;          // 0..767  (b*3 + c)
    const int b   = img / 3;
    const int lab = __ldg(label + b) & 3;

    const int bx = blockIdx.x;           // output tile col
    const int by = blockIdx.y;           // output tile row
    const int tx = threadIdx.x;          // 0..7   (float4 group within tile)
    const int ty = threadIdx.y;          // 0..31  (row within tile)

    // Fused label tail: one thread of one block per img writes label[img].
    if (out_tail != nullptr) {
        if (bx == 0 && by == 0 && tx == 0 && ty == 0 && img < n_tail)
            out_tail[img] = (float)__ldg(label + img);
    }

    const int ROW4 = HW / 4;             // 56 float4 per row
    const float4* __restrict__ in = x4   + (size_t)img * (HW * ROW4);
    float4* __restrict__       o  = out4 + (size_t)img * (HW * ROW4);

    __shared__ float tile[32][33];       // 33-float pitch: conflict-free

    if (lab == 0) {
        const int h = by * 32 + ty;
        const int g = bx * 8 + tx;
        o[h * ROW4 + g] = in[h * ROW4 + g];
    } else if (lab == 2) {
        const int h = by * 32 + ty;
        const int g = bx * 8 + tx;
        o[h * ROW4 + g] = in[(HW - 1 - h) * ROW4 + g];
    } else {
        // r90 / r270 share the transposed-gather structure.
        const int r = ty;                // input row within tile (0..31)
        const int src_row = (lab == 1) ? (bx * 32 + r)
                                       : (HW - 1 - (bx * 32 + r));
        const float4 v = in[src_row * ROW4 + (by * 8 + tx)];
        tile[r][4 * tx + 0] = v.x;
        tile[r][4 * tx + 1] = v.y;
        tile[r][4 * tx + 2] = v.z;
        tile[r][4 * tx + 3] = v.w;
        __syncthreads();

        const int i = ty;
        const int g = tx;
        float4 w;
        w.x = tile[4 * g + 0][i];
        w.y = tile[4 * g + 1][i];
        w.z = tile[4 * g + 2][i];
        w.w = tile[4 * g + 3][i];
        o[(by * 32 + i) * ROW4 + (bx * 8 + g)] = w;
    }
}

extern "C" void kernel_launch(void* const* d_in, const int* in_sizes, int n_in,
                              void* d_out, int out_size)
{
    const float4* x     = (const float4*)d_in[0];
    const int*    label = (const int*)d_in[1];
    float4*       out   = (float4*)d_out;

    const int  n_label   = (n_in > 1) ? in_sizes[1] : 256;
    const long img_elems = 256L * 3L * HW * HW;  // 38,535,168

    float* out_tail = nullptr;
    int    n_tail   = 0;
    if ((long)out_size > img_elems) {
        const int tail = (int)((long)out_size - img_elems);
        n_tail   = tail < n_label ? tail : n_label;
        out_tail = (float*)d_out + img_elems;
    }

    dim3 grid(TILES, TILES, 256 * 3);
    dim3 block(8, 32);
    rot_kernel<<<grid, block>>>(x, label, out, out_tail, n_tail);
}

// round 5
// speedup vs baseline: 1.1583x; 1.1583x over previous
#include <cuda_runtime.h>
#include <cstdint>

// Rotation42d: per-sample rotation of (256, 3, 224, 224) fp32 by label in {0,1,2,3}.
// One block handles one 32x32 tile across ALL 3 channels of a sample
// (channels share the label) -> 3 independent LDG.128 per thread (MLP=3).
// All global traffic 128-bit, streaming cache hints (no reuse).

#define HW 224
#define TILES 7          // 224/32
#define ROW4 56          // 224/4 float4 per row
#define CH_STRIDE (HW * ROW4)   // float4 per channel plane = 12544

__global__ __launch_bounds__(256) void rot_kernel(
    const float4* __restrict__ x4,
    const int*    __restrict__ label,
    float4*       __restrict__ out4,
    float*        __restrict__ out_tail,   // may be null
    int                         n_tail)
{
    const int b   = blockIdx.z;          // sample 0..255
    const int lab = __ldg(label + b) & 3;

    const int bx = blockIdx.x;           // output tile col
    const int by = blockIdx.y;           // output tile row
    const int tx = threadIdx.x;          // 0..7   (float4 group within tile)
    const int ty = threadIdx.y;          // 0..31  (row within tile)

    if (out_tail != nullptr) {
        if (bx == 0 && by == 0 && tx == 0 && ty == 0 && b < n_tail)
            out_tail[b] = (float)__ldg(label + b);
    }

    const float4* __restrict__ in = x4   + (size_t)b * (3 * CH_STRIDE);
    float4* __restrict__       o  = out4 + (size_t)b * (3 * CH_STRIDE);

    __shared__ float tile[3][32][33];    // +1 pad: conflict-free transposed reads

    if (lab == 0 || lab == 2) {
        const int h = by * 32 + ty;
        const int g = bx * 8 + tx;
        const int src = (lab == 0) ? (h * ROW4 + g) : ((HW - 1 - h) * ROW4 + g);
        const int dst = h * ROW4 + g;
        // 3 independent loads first (MLP), then 3 stores
        const float4 v0 = __ldcs(in + 0 * CH_STRIDE + src);
        const float4 v1 = __ldcs(in + 1 * CH_STRIDE + src);
        const float4 v2 = __ldcs(in + 2 * CH_STRIDE + src);
        __stcs(o + 0 * CH_STRIDE + dst, v0);
        __stcs(o + 1 * CH_STRIDE + dst, v1);
        __stcs(o + 2 * CH_STRIDE + dst, v2);
    } else {
        // r90 : out[h][w] = in[w][h]         -> tile[r][c] = in[bx*32+r][by*32+c]
        // r270: out[h][w] = in[HW-1-w][h]    -> tile[r][c] = in[HW-1-(bx*32+r)][by*32+c]
        const int r = ty;
        const int src_row = (lab == 1) ? (bx * 32 + r)
                                       : (HW - 1 - (bx * 32 + r));
        const int sidx = src_row * ROW4 + (by * 8 + tx);
        const float4 v0 = __ldcs(in + 0 * CH_STRIDE + sidx);
        const float4 v1 = __ldcs(in + 1 * CH_STRIDE + sidx);
        const float4 v2 = __ldcs(in + 2 * CH_STRIDE + sidx);
        #pragma unroll
        for (int k = 0; k < 4; k++) {
            tile[0][r][4 * tx + k] = ((const float*)&v0)[k];
            tile[1][r][4 * tx + k] = ((const float*)&v1)[k];
            tile[2][r][4 * tx + k] = ((const float*)&v2)[k];
        }
        __syncthreads();

        const int i = ty;
        const int g = tx;
        const int dst = (by * 32 + i) * ROW4 + (bx * 8 + g);
        #pragma unroll
        for (int ch = 0; ch < 3; ch++) {
            float4 w;
            w.x = tile[ch][4 * g + 0][i];
            w.y = tile[ch][4 * g + 1][i];
            w.z = tile[ch][4 * g + 2][i];
            w.w = tile[ch][4 * g + 3][i];
            __stcs(o + ch * CH_STRIDE + dst, w);
        }
    }
}

extern "C" void kernel_launch(void* const* d_in, const int* in_sizes, int n_in,
                              void* d_out, int out_size)
{
    const float4* x     = (const float4*)d_in[0];
    const int*    label = (const int*)d_in[1];
    float4*       out   = (float4*)d_out;

    const int  n_label   = (n_in > 1) ? in_sizes[1] : 256;
    const long img_elems = 256L * 3L * HW * HW;  // 38,535,168

    float* out_tail = nullptr;
    int    n_tail   = 0;
    if ((long)out_size > img_elems) {
        const int tail = (int)((long)out_size - img_elems);
        n_tail   = tail < n_label ? tail : n_label;
        out_tail = (float*)d_out + img_elems;
    }

    dim3 grid(TILES, TILES, 256);
    dim3 block(8, 32);
    rot_kernel<<<grid, block>>>(x, label, out, out_tail, n_tail);
}